// round 14
// baseline (speedup 1.0000x reference)
#include <cuda_runtime.h>
#include <cuda_fp16.h>
#include <cstdint>

#define NN 100000
#define NE 1600000
#define FEAT 64
#define ATTR 16
#define NRBF 8
#define SHD 9
#define NELEM 100
#define TAB 8192          // lerp intervals over r in [0,5]; row TAB == 0
#define NB_SCAN 391       // ceil(NN/256)
#define EPT 8             // edges per 16-thread slot

typedef unsigned long long ull;

// -------- persistent scratch --------
__device__ float   g_xattr[NN * ATTR];
__device__ __half2 g_hWh[NN * 32];               // h @ W_msg, fp16
__device__ float   g_agg[NN * FEAT];             // pre-activation accumulator (fp32)
__device__ float4  g_suvr[NE];                   // dst-sorted (ux,uy,uz,xf)
__device__ int2    g_ssd[NE];                    // dst-sorted (src, dst)
__device__ int     g_off[NN];                    // partial exclusive scan
__device__ int     g_cnt[NN];
__device__ int     g_cnt2[NN];
__device__ int     g_bsum[512];
__device__ int     g_bsumx[512];
__device__ __half2 g_rtabh[3][TAB + 1][32];      // radial tables, fp16

__device__ __forceinline__ float silu_f(float x) {
    return __fdividef(x, 1.0f + __expf(-x));
}

__device__ __forceinline__ void red4(float* p, float a, float b, float c, float d) {
    asm volatile("red.global.add.v4.f32 [%0], {%1,%2,%3,%4};"
                 :: "l"(p), "f"(a), "f"(b), "f"(c), "f"(d) : "memory");
}

// ---- packed f32x2 helpers (sm_100+) ----
__device__ __forceinline__ ull pk2(float lo, float hi) {
    ull d; asm("mov.b64 %0, {%1, %2};" : "=l"(d) : "f"(lo), "f"(hi)); return d;
}
__device__ __forceinline__ float2 upk2(ull a) {
    float2 f; asm("mov.b64 {%0, %1}, %2;" : "=f"(f.x), "=f"(f.y) : "l"(a)); return f;
}
__device__ __forceinline__ ull fma2(ull a, ull b, ull c) {
    ull d; asm("fma.rn.f32x2 %0, %1, %2, %3;" : "=l"(d) : "l"(a), "l"(b), "l"(c)); return d;
}
__device__ __forceinline__ ull mul2(ull a, ull b) {
    ull d; asm("mul.rn.f32x2 %0, %1, %2;" : "=l"(d) : "l"(a), "l"(b)); return d;
}
__device__ __forceinline__ ull h2_to_f32x2(unsigned h) {
    float2 f = __half22float2(*(const __half2*)&h);
    return pk2(f.x, f.y);
}

// ============================================================
// CSR build: histogram -> 2-step scan
// ============================================================
__global__ void k_hist(const int* __restrict__ eidx) {
    int e = blockIdx.x * 256 + threadIdx.x;
    if (e < NE) atomicAdd(&g_cnt[eidx[NE + e]], 1);
}

__global__ void k_scan1() {
    __shared__ int s[256];
    int i = blockIdx.x * 256 + threadIdx.x;
    int v = (i < NN) ? g_cnt[i] : 0;
    s[threadIdx.x] = v;
    __syncthreads();
    for (int d = 1; d < 256; d <<= 1) {
        int t = (threadIdx.x >= d) ? s[threadIdx.x - d] : 0;
        __syncthreads();
        s[threadIdx.x] += t;
        __syncthreads();
    }
    if (i < NN) g_off[i] = s[threadIdx.x] - v;
    if (threadIdx.x == 255) g_bsum[blockIdx.x] = s[255];
}

__global__ void k_scan2() {
    __shared__ int s[512];
    int tid = threadIdx.x;
    int v = (tid < NB_SCAN) ? g_bsum[tid] : 0;
    s[tid] = v;
    __syncthreads();
    for (int d = 1; d < 512; d <<= 1) {
        int t = (tid >= d) ? s[tid - d] : 0;
        __syncthreads();
        s[tid] += t;
        __syncthreads();
    }
    g_bsumx[tid] = s[tid] - v;
}

// ============================================================
// Edge geometry + scatter into dst-sorted arrays
// ============================================================
__global__ void k_prep(const int* __restrict__ eidx,
                       const float* __restrict__ pos,
                       const float* __restrict__ pvec) {
    int e = blockIdx.x * 256 + threadIdx.x;
    if (e >= NE) return;
    int s = eidx[e];
    int d = eidx[NE + e];
    float vx = __ldg(&pos[d * 3 + 0]) - __ldg(&pos[s * 3 + 0]) + pvec[e * 3 + 0];
    float vy = __ldg(&pos[d * 3 + 1]) - __ldg(&pos[s * 3 + 1]) + pvec[e * 3 + 1];
    float vz = __ldg(&pos[d * 3 + 2]) - __ldg(&pos[s * 3 + 2]) + pvec[e * 3 + 2];
    float r = sqrtf(vx * vx + vy * vy + vz * vz + 1e-12f);
    float inv = 1.0f / r;
    float xf = fminf(r * ((float)TAB * 0.2f), (float)TAB);
    int base = __ldg(&g_off[d]) + __ldg(&g_bsumx[d >> 8]);
    int idx = base + atomicAdd(&g_cnt2[d], 1);
    g_ssd[idx] = make_int2(s, d);
    g_suvr[idx] = make_float4(vx * inv, vy * inv, vz * inv, xf);
}

// ============================================================
// Radial table (fp16 store)
// ============================================================
__global__ void __launch_bounds__(256) k_radtab(const float* __restrict__ Wr1,
                                                const float* __restrict__ Wr2) {
    __shared__ float sR1[NRBF * FEAT];
    __shared__ float sR2[FEAT * FEAT];
    int l = blockIdx.y;
    for (int i = threadIdx.x; i < NRBF * FEAT; i += 256) sR1[i] = Wr1[l * NRBF * FEAT + i];
    for (int i = threadIdx.x; i < FEAT * FEAT; i += 256) sR2[i] = Wr2[l * FEAT * FEAT + i];
    __syncthreads();

    int i = blockIdx.x * 256 + threadIdx.x;
    if (i > TAB) return;
    float r = 5.0f * (float)i / (float)TAB;

    float rs = fmaxf(r, 1e-6f);
    float rp = r * 0.2f;
    float env = 0.0f;
    if (rp < 1.0f) {
        float rp2 = rp * rp, rp3 = rp2 * rp, rp6 = rp3 * rp3, rp7 = rp6 * rp, rp8 = rp7 * rp;
        env = 1.0f - 28.0f * rp6 + 48.0f * rp7 - 21.0f * rp8;
    }
    float pref = 0.6324555320336759f * env / rs;
    float base = 3.14159265358979323846f * rs * 0.2f;
    float rbf[NRBF];
#pragma unroll
    for (int n = 0; n < NRBF; n++) rbf[n] = pref * sinf((float)(n + 1) * base);

    float hid[FEAT];
#pragma unroll
    for (int j4 = 0; j4 < 16; j4++) {
        float ax = 0.f, ay = 0.f, az = 0.f, aw = 0.f;
#pragma unroll
        for (int k = 0; k < NRBF; k++) {
            const float4 w = *(const float4*)&sR1[k * FEAT + j4 * 4];
            float rv = rbf[k];
            ax = fmaf(rv, w.x, ax); ay = fmaf(rv, w.y, ay);
            az = fmaf(rv, w.z, az); aw = fmaf(rv, w.w, aw);
        }
        hid[j4 * 4 + 0] = silu_f(ax);
        hid[j4 * 4 + 1] = silu_f(ay);
        hid[j4 * 4 + 2] = silu_f(az);
        hid[j4 * 4 + 3] = silu_f(aw);
    }
    for (int c4 = 0; c4 < 16; c4++) {
        float rx = 0.f, ry = 0.f, rz = 0.f, rw = 0.f;
#pragma unroll
        for (int j = 0; j < FEAT; j++) {
            const float4 w = *(const float4*)&sR2[j * FEAT + c4 * 4];
            float hv = hid[j];
            rx = fmaf(hv, w.x, rx); ry = fmaf(hv, w.y, ry);
            rz = fmaf(hv, w.z, rz); rw = fmaf(hv, w.w, rw);
        }
        g_rtabh[l][i][c4 * 2 + 0] = __floats2half2_rn(rx, ry);
        g_rtabh[l][i][c4 * 2 + 1] = __floats2half2_rn(rz, rw);
    }
}

// ============================================================
// Embedding: h0 = elem_table[x] @ W_embed  (into d_out buffer)
// ============================================================
__global__ void k_embed(const int* __restrict__ x,
                        const float* __restrict__ elem_table,
                        const float* __restrict__ W_embed,
                        float* __restrict__ h) {
    __shared__ float sE[NELEM * ATTR];
    __shared__ float sW[ATTR * FEAT];
    for (int i = threadIdx.x; i < NELEM * ATTR; i += blockDim.x) sE[i] = elem_table[i];
    for (int i = threadIdx.x; i < ATTR * FEAT; i += blockDim.x) sW[i] = W_embed[i];
    __syncthreads();

    int t = blockIdx.x * blockDim.x + threadIdx.x;  // NN*16 exact
    int n = t >> 4;
    int c4 = t & 15;
    int xi = __ldg(&x[n]);
    float ax = 0.f, ay = 0.f, az = 0.f, aw = 0.f;
#pragma unroll
    for (int k = 0; k < ATTR; k++) {
        float a = sE[xi * ATTR + k];
        const float4 w = *(const float4*)&sW[k * FEAT + c4 * 4];
        ax = fmaf(a, w.x, ax); ay = fmaf(a, w.y, ay);
        az = fmaf(a, w.z, az); aw = fmaf(a, w.w, aw);
    }
    *(float4*)&h[n * FEAT + c4 * 4] = make_float4(ax, ay, az, aw);
    if (c4 < 4) {
        *(float4*)&g_xattr[n * ATTR + c4 * 4] = make_float4(
            sE[xi * ATTR + c4 * 4 + 0], sE[xi * ATTR + c4 * 4 + 1],
            sE[xi * ATTR + c4 * 4 + 2], sE[xi * ATTR + c4 * 4 + 3]);
    }
}

// ============================================================
// Node GEMMs, k-vectorized smem reads:
//   hW (fp16) = act(in) @ W_msg ; agg = act(in) @ W_self + x_attr @ W_attr
// ============================================================
#define HPAD 68
__global__ void __launch_bounds__(256) k_nodegemm(
        const float* __restrict__ in,
        int apply_silu,
        const float* __restrict__ Wm,
        const float* __restrict__ Ws,
        const float* __restrict__ Wa) {
    extern __shared__ float smem[];
    float* sH  = smem;
    float* sWm = sH + 64 * HPAD;
    float* sWs = sWm + FEAT * FEAT;
    float* sWa = sWs + FEAT * FEAT;

    int nb = blockIdx.x * 64;
    for (int idx = threadIdx.x; idx < 1024; idx += 256) {
        int n  = idx >> 4;
        int k0 = (idx & 15) * 4;
        float4 v = make_float4(0.f, 0.f, 0.f, 0.f);
        if (nb + n < NN) v = *(const float4*)&in[(nb + n) * FEAT + k0];
        if (apply_silu) {
            v.x = silu_f(v.x); v.y = silu_f(v.y);
            v.z = silu_f(v.z); v.w = silu_f(v.w);
        }
        *(float4*)&sH[n * HPAD + k0] = v;
    }
    for (int i = threadIdx.x; i < FEAT * FEAT; i += 256) { sWm[i] = Wm[i]; sWs[i] = Ws[i]; }
    for (int i = threadIdx.x; i < ATTR * FEAT; i += 256) sWa[i] = Wa[i];
    __syncthreads();

    int ng = threadIdx.x >> 4;
    int c4 = threadIdx.x & 15;

    float4 accM[4], accS[4];
#pragma unroll
    for (int i = 0; i < 4; i++) { accM[i] = make_float4(0,0,0,0); accS[i] = make_float4(0,0,0,0); }

#pragma unroll 4
    for (int k0 = 0; k0 < FEAT; k0 += 4) {
        float4 hv[4];
#pragma unroll
        for (int i = 0; i < 4; i++)
            hv[i] = *(const float4*)&sH[(ng * 4 + i) * HPAD + k0];
#pragma unroll
        for (int kk = 0; kk < 4; kk++) {
            const float4 wm = *(const float4*)&sWm[(k0 + kk) * FEAT + c4 * 4];
            const float4 ws = *(const float4*)&sWs[(k0 + kk) * FEAT + c4 * 4];
#pragma unroll
            for (int i = 0; i < 4; i++) {
                const float* hp = (const float*)&hv[i];
                float hvk = hp[kk];
                accM[i].x = fmaf(hvk, wm.x, accM[i].x); accM[i].y = fmaf(hvk, wm.y, accM[i].y);
                accM[i].z = fmaf(hvk, wm.z, accM[i].z); accM[i].w = fmaf(hvk, wm.w, accM[i].w);
                accS[i].x = fmaf(hvk, ws.x, accS[i].x); accS[i].y = fmaf(hvk, ws.y, accS[i].y);
                accS[i].z = fmaf(hvk, ws.z, accS[i].z); accS[i].w = fmaf(hvk, ws.w, accS[i].w);
            }
        }
    }
    int ni[4];
#pragma unroll
    for (int i = 0; i < 4; i++) ni[i] = min(nb + ng * 4 + i, NN - 1);
#pragma unroll
    for (int k = 0; k < ATTR; k++) {
        const float4 wa = *(const float4*)&sWa[k * FEAT + c4 * 4];
#pragma unroll
        for (int i = 0; i < 4; i++) {
            float av = __ldg(&g_xattr[ni[i] * ATTR + k]);
            accS[i].x = fmaf(av, wa.x, accS[i].x); accS[i].y = fmaf(av, wa.y, accS[i].y);
            accS[i].z = fmaf(av, wa.z, accS[i].z); accS[i].w = fmaf(av, wa.w, accS[i].w);
        }
    }
#pragma unroll
    for (int i = 0; i < 4; i++) {
        int n = nb + ng * 4 + i;
        if (n < NN) {
            __half2 p0 = __floats2half2_rn(accM[i].x, accM[i].y);
            __half2 p1 = __floats2half2_rn(accM[i].z, accM[i].w);
            *(uint2*)&g_hWh[n * 32 + c4 * 2] = make_uint2(
                *(const unsigned*)&p0, *(const unsigned*)&p1);
            *(float4*)&g_agg[n * FEAT + c4 * 4] = accS[i];
        }
    }
}

// ============================================================
// Segmented edge kernel with packed f32x2 math.
// ============================================================
#define EDGE_BLOCKS (NE / EPT * 16 / 256)   // 12500
__global__ void __launch_bounds__(256) k_edge(const float* __restrict__ Wsh,
                                              const __half2* __restrict__ rtab) {
    int t = blockIdx.x * 256 + threadIdx.x;
    int c4 = t & 15;
    int slot = t >> 4;
    int e0 = slot * EPT;

    ull wshp01[SHD], wshp23[SHD];
#pragma unroll
    for (int m = 0; m < SHD; m++) {
        const float4 w = __ldg((const float4*)&Wsh[m * FEAT + c4 * 4]);
        wshp01[m] = pk2(w.x, w.y);
        wshp23[m] = pk2(w.z, w.w);
    }

    const float s3    = 1.7320508075688772f;
    const float s15   = 3.872983346207417f;
    const float s5_4  = 1.118033988749895f;
    const float s15_4 = 1.936491673103708f;

    int cur = __ldg(&g_ssd[e0]).y;
    ull acc01 = 0ULL, acc23 = 0ULL;   // (0.0f, 0.0f) packed

#pragma unroll 4
    for (int e = e0; e < e0 + EPT; e++) {
        const int2 sd = __ldg(&g_ssd[e]);
        if (sd.y != cur) {
            float2 a01 = upk2(acc01), a23 = upk2(acc23);
            red4(&g_agg[cur * FEAT + c4 * 4], a01.x, a01.y, a23.x, a23.y);
            acc01 = 0ULL; acc23 = 0ULL;
            cur = sd.y;
        }
        const float4 uvr = __ldg(&g_suvr[e]);
        float ux = uvr.x, uy = uvr.y, uz = uvr.z, xf = uvr.w;

        int   i0 = min((int)xf, TAB - 1);
        float fr = xf - (float)i0;
        const uint2 t0b = __ldg((const uint2*)&rtab[i0 * 32 + c4 * 2]);
        const uint2 t1b = __ldg((const uint2*)&rtab[(i0 + 1) * 32 + c4 * 2]);
        ull t0_01 = h2_to_f32x2(t0b.x);
        ull t0_23 = h2_to_f32x2(t0b.y);
        ull t1_01 = h2_to_f32x2(t1b.x);
        ull t1_23 = h2_to_f32x2(t1b.y);

        ull fr2  = pk2(fr, fr);
        ull nfr2 = pk2(-fr, -fr);
        // rad = t0*(1-fr) + t1*fr  (2 packed fma per pair)
        ull rad01 = fma2(fr2, t1_01, fma2(nfr2, t0_01, t0_01));
        ull rad23 = fma2(fr2, t1_23, fma2(nfr2, t0_23, t0_23));

        // SH basis (scalar, lane-redundant but cheap)
        float sh1 = s3 * ux, sh2 = s3 * uy, sh3 = s3 * uz;
        float sh4 = s15 * ux * uy, sh5 = s15 * uy * uz;
        float sh6 = s5_4 * (3.0f * uz * uz - 1.0f);
        float sh7 = s15 * ux * uz;
        float sh8 = s15_4 * (ux * ux - uy * uy);

        ull m01 = wshp01[0], m23 = wshp23[0];  // sh0 == 1
        ull s2v;
        s2v = pk2(sh1, sh1); m01 = fma2(s2v, wshp01[1], m01); m23 = fma2(s2v, wshp23[1], m23);
        s2v = pk2(sh2, sh2); m01 = fma2(s2v, wshp01[2], m01); m23 = fma2(s2v, wshp23[2], m23);
        s2v = pk2(sh3, sh3); m01 = fma2(s2v, wshp01[3], m01); m23 = fma2(s2v, wshp23[3], m23);
        s2v = pk2(sh4, sh4); m01 = fma2(s2v, wshp01[4], m01); m23 = fma2(s2v, wshp23[4], m23);
        s2v = pk2(sh5, sh5); m01 = fma2(s2v, wshp01[5], m01); m23 = fma2(s2v, wshp23[5], m23);
        s2v = pk2(sh6, sh6); m01 = fma2(s2v, wshp01[6], m01); m23 = fma2(s2v, wshp23[6], m23);
        s2v = pk2(sh7, sh7); m01 = fma2(s2v, wshp01[7], m01); m23 = fma2(s2v, wshp23[7], m23);
        s2v = pk2(sh8, sh8); m01 = fma2(s2v, wshp01[8], m01); m23 = fma2(s2v, wshp23[8], m23);

        const uint2 hwb = __ldg((const uint2*)&g_hWh[sd.x * 32 + c4 * 2]);
        ull hw01 = h2_to_f32x2(hwb.x);
        ull hw23 = h2_to_f32x2(hwb.y);

        acc01 = fma2(mul2(hw01, rad01), m01, acc01);
        acc23 = fma2(mul2(hw23, rad23), m23, acc23);
    }
    float2 a01 = upk2(acc01), a23 = upk2(acc23);
    red4(&g_agg[cur * FEAT + c4 * 4], a01.x, a01.y, a23.x, a23.y);
}

// ============================================================
// Final activation: d_out = silu(agg)
// ============================================================
__global__ void k_fin(float* __restrict__ h) {
    int t = blockIdx.x * blockDim.x + threadIdx.x;
    const float4 v = *(const float4*)&g_agg[t * 4];
    *(float4*)&h[t * 4] = make_float4(silu_f(v.x), silu_f(v.y), silu_f(v.z), silu_f(v.w));
}

// ============================================================
extern "C" void kernel_launch(void* const* d_in, const int* in_sizes, int n_in,
                              void* d_out, int out_size) {
    const int* x       = (const int*)d_in[0];
    const float* pos   = (const float*)d_in[1];
    const int* eidx    = (const int*)d_in[2];
    const float* pvec  = (const float*)d_in[3];
    // d_in[4] = batch (unused)
    const float* elem  = (const float*)d_in[5];
    const float* Wemb  = (const float*)d_in[6];
    const float* Wattr = (const float*)d_in[7];
    const float* Wself = (const float*)d_in[8];
    const float* Wmsg  = (const float*)d_in[9];
    const float* Wr1   = (const float*)d_in[10];
    const float* Wr2   = (const float*)d_in[11];
    const float* Wsh   = (const float*)d_in[12];
    float* h = (float*)d_out;

    __half2* rtab_base;
    float* agg_base;
    void* cnt_base;
    void* cnt2_base;
    cudaGetSymbolAddress((void**)&rtab_base, g_rtabh);
    cudaGetSymbolAddress((void**)&agg_base, g_agg);
    cudaGetSymbolAddress(&cnt_base, g_cnt);
    cudaGetSymbolAddress(&cnt2_base, g_cnt2);

    const int NG_SMEM = (64 * HPAD + FEAT * FEAT * 2 + ATTR * FEAT) * 4;  // 54272 B
    cudaFuncSetAttribute(k_nodegemm, cudaFuncAttributeMaxDynamicSharedMemorySize, NG_SMEM);

    // CSR build (counters re-zeroed every call -> deterministic)
    cudaMemsetAsync(cnt_base, 0, NN * sizeof(int));
    cudaMemsetAsync(cnt2_base, 0, NN * sizeof(int));
    k_hist<<<(NE + 255) / 256, 256>>>(eidx);
    k_scan1<<<NB_SCAN, 256>>>();
    k_scan2<<<1, 512>>>();
    k_prep<<<(NE + 255) / 256, 256>>>(eidx, pos, pvec);

    k_radtab<<<dim3((TAB + 1 + 255) / 256, 3), 256>>>(Wr1, Wr2);
    k_embed<<<NN * 16 / 256, 256>>>(x, elem, Wemb, h);

    for (int l = 0; l < 3; l++) {
        k_nodegemm<<<(NN + 63) / 64, 256, NG_SMEM>>>(
            (l == 0) ? h : agg_base, (l == 0) ? 0 : 1,
            Wmsg + l * FEAT * FEAT, Wself + l * FEAT * FEAT, Wattr + l * ATTR * FEAT);
        k_edge<<<EDGE_BLOCKS, 256>>>(Wsh + l * SHD * FEAT,
                                     rtab_base + l * (TAB + 1) * 32);
    }
    k_fin<<<NN * 16 / 256, 256>>>(h);
}

// round 15
// speedup vs baseline: 1.1119x; 1.1119x over previous
#include <cuda_runtime.h>
#include <cuda_fp16.h>
#include <cstdint>

#define NN 100000
#define NE 1600000
#define FEAT 64
#define ATTR 16
#define NRBF 8
#define SHD 9
#define NELEM 100
#define TAB 8192          // lerp intervals over r in [0,5]; row TAB == 0
#define NB_SCAN 391       // ceil(NN/256)
#define EPT 8             // edges per 16-thread slot

// -------- persistent scratch --------
__device__ float   g_xattr[NN * ATTR];
__device__ __half2 g_hWh[NN * 32];               // h @ W_msg, fp16
__device__ float   g_agg[NN * FEAT];             // pre-activation accumulator (fp32)
__device__ float4  g_suvr[NE];                   // dst-sorted (ux,uy,uz,xf)
__device__ int2    g_ssd[NE];                    // dst-sorted (src, dst)
__device__ int     g_off[NN];                    // partial exclusive scan
__device__ int     g_cnt[NN];
__device__ int     g_cnt2[NN];
__device__ int     g_bsum[512];
__device__ int     g_bsumx[512];
__device__ __half2 g_rtabh[3][TAB + 1][32];      // radial tables, fp16

__device__ __forceinline__ float silu_f(float x) {
    return __fdividef(x, 1.0f + __expf(-x));
}

__device__ __forceinline__ void red4(float* p, float a, float b, float c, float d) {
    asm volatile("red.global.add.v4.f32 [%0], {%1,%2,%3,%4};"
                 :: "l"(p), "f"(a), "f"(b), "f"(c), "f"(d) : "memory");
}

// ============================================================
// CSR build: histogram -> 2-step scan
// ============================================================
__global__ void k_hist(const int* __restrict__ eidx) {
    int e = blockIdx.x * 256 + threadIdx.x;
    if (e < NE) atomicAdd(&g_cnt[eidx[NE + e]], 1);
}

__global__ void k_scan1() {
    __shared__ int s[256];
    int i = blockIdx.x * 256 + threadIdx.x;
    int v = (i < NN) ? g_cnt[i] : 0;
    s[threadIdx.x] = v;
    __syncthreads();
    for (int d = 1; d < 256; d <<= 1) {
        int t = (threadIdx.x >= d) ? s[threadIdx.x - d] : 0;
        __syncthreads();
        s[threadIdx.x] += t;
        __syncthreads();
    }
    if (i < NN) g_off[i] = s[threadIdx.x] - v;
    if (threadIdx.x == 255) g_bsum[blockIdx.x] = s[255];
}

__global__ void k_scan2() {
    __shared__ int s[512];
    int tid = threadIdx.x;
    int v = (tid < NB_SCAN) ? g_bsum[tid] : 0;
    s[tid] = v;
    __syncthreads();
    for (int d = 1; d < 512; d <<= 1) {
        int t = (tid >= d) ? s[tid - d] : 0;
        __syncthreads();
        s[tid] += t;
        __syncthreads();
    }
    g_bsumx[tid] = s[tid] - v;
}

// ============================================================
// Edge geometry + scatter into dst-sorted arrays
// ============================================================
__global__ void k_prep(const int* __restrict__ eidx,
                       const float* __restrict__ pos,
                       const float* __restrict__ pvec) {
    int e = blockIdx.x * 256 + threadIdx.x;
    if (e >= NE) return;
    int s = eidx[e];
    int d = eidx[NE + e];
    float vx = __ldg(&pos[d * 3 + 0]) - __ldg(&pos[s * 3 + 0]) + pvec[e * 3 + 0];
    float vy = __ldg(&pos[d * 3 + 1]) - __ldg(&pos[s * 3 + 1]) + pvec[e * 3 + 1];
    float vz = __ldg(&pos[d * 3 + 2]) - __ldg(&pos[s * 3 + 2]) + pvec[e * 3 + 2];
    float r = sqrtf(vx * vx + vy * vy + vz * vz + 1e-12f);
    float inv = 1.0f / r;
    float xf = fminf(r * ((float)TAB * 0.2f), (float)TAB);
    int base = __ldg(&g_off[d]) + __ldg(&g_bsumx[d >> 8]);
    int idx = base + atomicAdd(&g_cnt2[d], 1);
    g_ssd[idx] = make_int2(s, d);
    g_suvr[idx] = make_float4(vx * inv, vy * inv, vz * inv, xf);
}

// ============================================================
// Radial table (fp16 store)
// ============================================================
__global__ void __launch_bounds__(256) k_radtab(const float* __restrict__ Wr1,
                                                const float* __restrict__ Wr2) {
    __shared__ float sR1[NRBF * FEAT];
    __shared__ float sR2[FEAT * FEAT];
    int l = blockIdx.y;
    for (int i = threadIdx.x; i < NRBF * FEAT; i += 256) sR1[i] = Wr1[l * NRBF * FEAT + i];
    for (int i = threadIdx.x; i < FEAT * FEAT; i += 256) sR2[i] = Wr2[l * FEAT * FEAT + i];
    __syncthreads();

    int i = blockIdx.x * 256 + threadIdx.x;
    if (i > TAB) return;
    float r = 5.0f * (float)i / (float)TAB;

    float rs = fmaxf(r, 1e-6f);
    float rp = r * 0.2f;
    float env = 0.0f;
    if (rp < 1.0f) {
        float rp2 = rp * rp, rp3 = rp2 * rp, rp6 = rp3 * rp3, rp7 = rp6 * rp, rp8 = rp7 * rp;
        env = 1.0f - 28.0f * rp6 + 48.0f * rp7 - 21.0f * rp8;
    }
    float pref = 0.6324555320336759f * env / rs;
    float base = 3.14159265358979323846f * rs * 0.2f;
    float rbf[NRBF];
#pragma unroll
    for (int n = 0; n < NRBF; n++) rbf[n] = pref * sinf((float)(n + 1) * base);

    float hid[FEAT];
#pragma unroll
    for (int j4 = 0; j4 < 16; j4++) {
        float ax = 0.f, ay = 0.f, az = 0.f, aw = 0.f;
#pragma unroll
        for (int k = 0; k < NRBF; k++) {
            const float4 w = *(const float4*)&sR1[k * FEAT + j4 * 4];
            float rv = rbf[k];
            ax = fmaf(rv, w.x, ax); ay = fmaf(rv, w.y, ay);
            az = fmaf(rv, w.z, az); aw = fmaf(rv, w.w, aw);
        }
        hid[j4 * 4 + 0] = silu_f(ax);
        hid[j4 * 4 + 1] = silu_f(ay);
        hid[j4 * 4 + 2] = silu_f(az);
        hid[j4 * 4 + 3] = silu_f(aw);
    }
    for (int c4 = 0; c4 < 16; c4++) {
        float rx = 0.f, ry = 0.f, rz = 0.f, rw = 0.f;
#pragma unroll
        for (int j = 0; j < FEAT; j++) {
            const float4 w = *(const float4*)&sR2[j * FEAT + c4 * 4];
            float hv = hid[j];
            rx = fmaf(hv, w.x, rx); ry = fmaf(hv, w.y, ry);
            rz = fmaf(hv, w.z, rz); rw = fmaf(hv, w.w, rw);
        }
        g_rtabh[l][i][c4 * 2 + 0] = __floats2half2_rn(rx, ry);
        g_rtabh[l][i][c4 * 2 + 1] = __floats2half2_rn(rz, rw);
    }
}

// ============================================================
// Embedding: h0 = elem_table[x] @ W_embed  (into d_out buffer)
// ============================================================
__global__ void k_embed(const int* __restrict__ x,
                        const float* __restrict__ elem_table,
                        const float* __restrict__ W_embed,
                        float* __restrict__ h) {
    __shared__ float sE[NELEM * ATTR];
    __shared__ float sW[ATTR * FEAT];
    for (int i = threadIdx.x; i < NELEM * ATTR; i += blockDim.x) sE[i] = elem_table[i];
    for (int i = threadIdx.x; i < ATTR * FEAT; i += blockDim.x) sW[i] = W_embed[i];
    __syncthreads();

    int t = blockIdx.x * blockDim.x + threadIdx.x;  // NN*16 exact
    int n = t >> 4;
    int c4 = t & 15;
    int xi = __ldg(&x[n]);
    float ax = 0.f, ay = 0.f, az = 0.f, aw = 0.f;
#pragma unroll
    for (int k = 0; k < ATTR; k++) {
        float a = sE[xi * ATTR + k];
        const float4 w = *(const float4*)&sW[k * FEAT + c4 * 4];
        ax = fmaf(a, w.x, ax); ay = fmaf(a, w.y, ay);
        az = fmaf(a, w.z, az); aw = fmaf(a, w.w, aw);
    }
    *(float4*)&h[n * FEAT + c4 * 4] = make_float4(ax, ay, az, aw);
    if (c4 < 4) {
        *(float4*)&g_xattr[n * ATTR + c4 * 4] = make_float4(
            sE[xi * ATTR + c4 * 4 + 0], sE[xi * ATTR + c4 * 4 + 1],
            sE[xi * ATTR + c4 * 4 + 2], sE[xi * ATTR + c4 * 4 + 3]);
    }
}

// ============================================================
// Node GEMMs, k-vectorized smem reads:
//   hW (fp16) = act(in) @ W_msg ; agg = act(in) @ W_self + x_attr @ W_attr
// ============================================================
#define HPAD 68
__global__ void __launch_bounds__(256) k_nodegemm(
        const float* __restrict__ in,
        int apply_silu,
        const float* __restrict__ Wm,
        const float* __restrict__ Ws,
        const float* __restrict__ Wa) {
    extern __shared__ float smem[];
    float* sH  = smem;
    float* sWm = sH + 64 * HPAD;
    float* sWs = sWm + FEAT * FEAT;
    float* sWa = sWs + FEAT * FEAT;

    int nb = blockIdx.x * 64;
    for (int idx = threadIdx.x; idx < 1024; idx += 256) {
        int n  = idx >> 4;
        int k0 = (idx & 15) * 4;
        float4 v = make_float4(0.f, 0.f, 0.f, 0.f);
        if (nb + n < NN) v = *(const float4*)&in[(nb + n) * FEAT + k0];
        if (apply_silu) {
            v.x = silu_f(v.x); v.y = silu_f(v.y);
            v.z = silu_f(v.z); v.w = silu_f(v.w);
        }
        *(float4*)&sH[n * HPAD + k0] = v;
    }
    for (int i = threadIdx.x; i < FEAT * FEAT; i += 256) { sWm[i] = Wm[i]; sWs[i] = Ws[i]; }
    for (int i = threadIdx.x; i < ATTR * FEAT; i += 256) sWa[i] = Wa[i];
    __syncthreads();

    int ng = threadIdx.x >> 4;
    int c4 = threadIdx.x & 15;

    float4 accM[4], accS[4];
#pragma unroll
    for (int i = 0; i < 4; i++) { accM[i] = make_float4(0,0,0,0); accS[i] = make_float4(0,0,0,0); }

#pragma unroll 4
    for (int k0 = 0; k0 < FEAT; k0 += 4) {
        float4 hv[4];
#pragma unroll
        for (int i = 0; i < 4; i++)
            hv[i] = *(const float4*)&sH[(ng * 4 + i) * HPAD + k0];
#pragma unroll
        for (int kk = 0; kk < 4; kk++) {
            const float4 wm = *(const float4*)&sWm[(k0 + kk) * FEAT + c4 * 4];
            const float4 ws = *(const float4*)&sWs[(k0 + kk) * FEAT + c4 * 4];
#pragma unroll
            for (int i = 0; i < 4; i++) {
                const float* hp = (const float*)&hv[i];
                float hvk = hp[kk];
                accM[i].x = fmaf(hvk, wm.x, accM[i].x); accM[i].y = fmaf(hvk, wm.y, accM[i].y);
                accM[i].z = fmaf(hvk, wm.z, accM[i].z); accM[i].w = fmaf(hvk, wm.w, accM[i].w);
                accS[i].x = fmaf(hvk, ws.x, accS[i].x); accS[i].y = fmaf(hvk, ws.y, accS[i].y);
                accS[i].z = fmaf(hvk, ws.z, accS[i].z); accS[i].w = fmaf(hvk, ws.w, accS[i].w);
            }
        }
    }
    int ni[4];
#pragma unroll
    for (int i = 0; i < 4; i++) ni[i] = min(nb + ng * 4 + i, NN - 1);
#pragma unroll
    for (int k = 0; k < ATTR; k++) {
        const float4 wa = *(const float4*)&sWa[k * FEAT + c4 * 4];
#pragma unroll
        for (int i = 0; i < 4; i++) {
            float av = __ldg(&g_xattr[ni[i] * ATTR + k]);
            accS[i].x = fmaf(av, wa.x, accS[i].x); accS[i].y = fmaf(av, wa.y, accS[i].y);
            accS[i].z = fmaf(av, wa.z, accS[i].z); accS[i].w = fmaf(av, wa.w, accS[i].w);
        }
    }
#pragma unroll
    for (int i = 0; i < 4; i++) {
        int n = nb + ng * 4 + i;
        if (n < NN) {
            __half2 p0 = __floats2half2_rn(accM[i].x, accM[i].y);
            __half2 p1 = __floats2half2_rn(accM[i].z, accM[i].w);
            *(uint2*)&g_hWh[n * 32 + c4 * 2] = make_uint2(
                *(const unsigned*)&p0, *(const unsigned*)&p1);
            *(float4*)&g_agg[n * FEAT + c4 * 4] = accS[i];
        }
    }
}

// ============================================================
// Segmented edge kernel (R13 structure): 16-lane slot owns EPT
// consecutive dst-sorted edges. sh-mix in HFMA2 (operands born
// packed: half2 Wsh hoisted, SH basis computed in dup-half2).
// Lerp / product / accumulate stay fp32.
// ============================================================
#define EDGE_BLOCKS (NE / EPT * 16 / 256)   // 12500
__global__ void __launch_bounds__(256) k_edge(const float* __restrict__ Wsh,
                                              const __half2* __restrict__ rtab) {
    int t = blockIdx.x * 256 + threadIdx.x;
    int c4 = t & 15;
    int slot = t >> 4;
    int e0 = slot * EPT;

    // Wsh quad pre-packed to half2 (hoisted; amortized over EPT edges)
    __half2 wh0[SHD], wh1[SHD];
#pragma unroll
    for (int m = 0; m < SHD; m++) {
        const float4 w = __ldg((const float4*)&Wsh[m * FEAT + c4 * 4]);
        wh0[m] = __floats2half2_rn(w.x, w.y);
        wh1[m] = __floats2half2_rn(w.z, w.w);
    }

    const __half2 hs3   = __float2half2_rn(1.7320508075688772f);
    const __half2 hs15  = __float2half2_rn(3.872983346207417f);
    const __half2 hs54  = __float2half2_rn(1.118033988749895f);
    const __half2 hs154 = __float2half2_rn(1.936491673103708f);
    const __half2 hthree = __float2half2_rn(3.0f);
    const __half2 hnone  = __float2half2_rn(-1.0f);

    int cur = __ldg(&g_ssd[e0]).y;
    float ax = 0.f, ay = 0.f, az = 0.f, aw = 0.f;

#pragma unroll 4
    for (int e = e0; e < e0 + EPT; e++) {
        const int2 sd = __ldg(&g_ssd[e]);
        if (sd.y != cur) {
            red4(&g_agg[cur * FEAT + c4 * 4], ax, ay, az, aw);
            ax = ay = az = aw = 0.f;
            cur = sd.y;
        }
        const float4 uvr = __ldg(&g_suvr[e]);
        float xf = uvr.w;

        // radial via fp16 table + fp32 lerp
        int   i0 = min((int)xf, TAB - 1);
        float fr = xf - (float)i0;
        const uint2 t0b = __ldg((const uint2*)&rtab[i0 * 32 + c4 * 2]);
        const uint2 t1b = __ldg((const uint2*)&rtab[(i0 + 1) * 32 + c4 * 2]);
        float2 t0a = __half22float2(*(const __half2*)&t0b.x);
        float2 t0c = __half22float2(*(const __half2*)&t0b.y);
        float2 t1a = __half22float2(*(const __half2*)&t1b.x);
        float2 t1c = __half22float2(*(const __half2*)&t1b.y);
        float radx = fmaf(fr, t1a.x - t0a.x, t0a.x);
        float rady = fmaf(fr, t1a.y - t0a.y, t0a.y);
        float radz = fmaf(fr, t1c.x - t0c.x, t0c.x);
        float radw = fmaf(fr, t1c.y - t0c.y, t0c.y);

        // SH basis in duplicated half2 (3 cvt + 12 half2 ops)
        __half2 hux = __float2half2_rn(uvr.x);
        __half2 huy = __float2half2_rn(uvr.y);
        __half2 huz = __float2half2_rn(uvr.z);
        __half2 hsh1 = __hmul2(hs3, hux);
        __half2 hsh2 = __hmul2(hs3, huy);
        __half2 hsh3 = __hmul2(hs3, huz);
        __half2 t15x = __hmul2(hs15, hux);
        __half2 hsh4 = __hmul2(t15x, huy);
        __half2 hsh7 = __hmul2(t15x, huz);
        __half2 hsh5 = __hmul2(__hmul2(hs15, huy), huz);
        __half2 uz2  = __hmul2(huz, huz);
        __half2 hsh6 = __hmul2(hs54, __hfma2(hthree, uz2, hnone));
        __half2 ux2  = __hmul2(hux, hux);
        __half2 hsh8 = __hmul2(hs154, __hsub2(ux2, __hmul2(huy, huy)));

        // mix = sh @ Wsh in HFMA2 (16 ops instead of 36 FFMA)
        __half2 m0 = wh0[0], m1 = wh1[0];    // sh0 == 1
        m0 = __hfma2(hsh1, wh0[1], m0); m1 = __hfma2(hsh1, wh1[1], m1);
        m0 = __hfma2(hsh2, wh0[2], m0); m1 = __hfma2(hsh2, wh1[2], m1);
        m0 = __hfma2(hsh3, wh0[3], m0); m1 = __hfma2(hsh3, wh1[3], m1);
        m0 = __hfma2(hsh4, wh0[4], m0); m1 = __hfma2(hsh4, wh1[4], m1);
        m0 = __hfma2(hsh5, wh0[5], m0); m1 = __hfma2(hsh5, wh1[5], m1);
        m0 = __hfma2(hsh6, wh0[6], m0); m1 = __hfma2(hsh6, wh1[6], m1);
        m0 = __hfma2(hsh7, wh0[7], m0); m1 = __hfma2(hsh7, wh1[7], m1);
        m0 = __hfma2(hsh8, wh0[8], m0); m1 = __hfma2(hsh8, wh1[8], m1);
        float2 mx01 = __half22float2(m0);
        float2 mx23 = __half22float2(m1);

        const uint2 hwb = __ldg((const uint2*)&g_hWh[sd.x * 32 + c4 * 2]);
        float2 hw01 = __half22float2(*(const __half2*)&hwb.x);
        float2 hw23 = __half22float2(*(const __half2*)&hwb.y);

        ax = fmaf(hw01.x * radx, mx01.x, ax);
        ay = fmaf(hw01.y * rady, mx01.y, ay);
        az = fmaf(hw23.x * radz, mx23.x, az);
        aw = fmaf(hw23.y * radw, mx23.y, aw);
    }
    red4(&g_agg[cur * FEAT + c4 * 4], ax, ay, az, aw);
}

// ============================================================
// Final activation: d_out = silu(agg)
// ============================================================
__global__ void k_fin(float* __restrict__ h) {
    int t = blockIdx.x * blockDim.x + threadIdx.x;
    const float4 v = *(const float4*)&g_agg[t * 4];
    *(float4*)&h[t * 4] = make_float4(silu_f(v.x), silu_f(v.y), silu_f(v.z), silu_f(v.w));
}

// ============================================================
extern "C" void kernel_launch(void* const* d_in, const int* in_sizes, int n_in,
                              void* d_out, int out_size) {
    const int* x       = (const int*)d_in[0];
    const float* pos   = (const float*)d_in[1];
    const int* eidx    = (const int*)d_in[2];
    const float* pvec  = (const float*)d_in[3];
    // d_in[4] = batch (unused)
    const float* elem  = (const float*)d_in[5];
    const float* Wemb  = (const float*)d_in[6];
    const float* Wattr = (const float*)d_in[7];
    const float* Wself = (const float*)d_in[8];
    const float* Wmsg  = (const float*)d_in[9];
    const float* Wr1   = (const float*)d_in[10];
    const float* Wr2   = (const float*)d_in[11];
    const float* Wsh   = (const float*)d_in[12];
    float* h = (float*)d_out;

    __half2* rtab_base;
    float* agg_base;
    void* cnt_base;
    void* cnt2_base;
    cudaGetSymbolAddress((void**)&rtab_base, g_rtabh);
    cudaGetSymbolAddress((void**)&agg_base, g_agg);
    cudaGetSymbolAddress(&cnt_base, g_cnt);
    cudaGetSymbolAddress(&cnt2_base, g_cnt2);

    const int NG_SMEM = (64 * HPAD + FEAT * FEAT * 2 + ATTR * FEAT) * 4;  // 54272 B
    cudaFuncSetAttribute(k_nodegemm, cudaFuncAttributeMaxDynamicSharedMemorySize, NG_SMEM);

    // CSR build (counters re-zeroed every call -> deterministic)
    cudaMemsetAsync(cnt_base, 0, NN * sizeof(int));
    cudaMemsetAsync(cnt2_base, 0, NN * sizeof(int));
    k_hist<<<(NE + 255) / 256, 256>>>(eidx);
    k_scan1<<<NB_SCAN, 256>>>();
    k_scan2<<<1, 512>>>();
    k_prep<<<(NE + 255) / 256, 256>>>(eidx, pos, pvec);

    k_radtab<<<dim3((TAB + 1 + 255) / 256, 3), 256>>>(Wr1, Wr2);
    k_embed<<<NN * 16 / 256, 256>>>(x, elem, Wemb, h);

    for (int l = 0; l < 3; l++) {
        k_nodegemm<<<(NN + 63) / 64, 256, NG_SMEM>>>(
            (l == 0) ? h : agg_base, (l == 0) ? 0 : 1,
            Wmsg + l * FEAT * FEAT, Wself + l * FEAT * FEAT, Wattr + l * ATTR * FEAT);
        k_edge<<<EDGE_BLOCKS, 256>>>(Wsh + l * SHD * FEAT,
                                     rtab_base + l * (TAB + 1) * 32);
    }
    k_fin<<<NN * 16 / 256, 256>>>(h);
}